// round 1
// baseline (speedup 1.0000x reference)
#include <cuda_runtime.h>
#include <math.h>

#define CD 384
#define FFD 1536
#define NHEAD 12
#define DHEAD 32
#define TMAX (32*64*64)   // 131072 tokens (B=32 fixed by setup_inputs)

// ---------------- scratch (static device globals; no allocations) ----------
__device__ float g_win[(size_t)TMAX * CD];
__device__ float g_lnq[(size_t)TMAX * CD];
__device__ float g_lnk[(size_t)TMAX * CD];
__device__ float g_lnv[(size_t)TMAX * CD];
__device__ float g_q  [(size_t)TMAX * CD];
__device__ float g_k  [(size_t)TMAX * CD];
__device__ float g_v  [(size_t)TMAX * CD];
__device__ float g_h  [(size_t)TMAX * FFD];

// ---------------- block-wide (128 thr) sum of two values -------------------
__device__ __forceinline__ void reduce2_128(float& s0, float& s1, float* sm) {
    #pragma unroll
    for (int o = 16; o > 0; o >>= 1) {
        s0 += __shfl_down_sync(0xffffffffu, s0, o);
        s1 += __shfl_down_sync(0xffffffffu, s1, o);
    }
    int w = threadIdx.x >> 5;
    if ((threadIdx.x & 31) == 0) { sm[w] = s0; sm[4 + w] = s1; }
    __syncthreads();
    s0 = sm[0] + sm[1] + sm[2] + sm[3];
    s1 = sm[4] + sm[5] + sm[6] + sm[7];
    __syncthreads();
}

// win-layout token t -> x-layout flat row index
__device__ __forceinline__ int t_to_xrow(int t) {
    int w = t >> 6, l = t & 63;
    int b = w >> 6, wi = w & 63;
    int wy = wi >> 3, wx = wi & 7;
    int iy = l >> 3, ix = l & 7;
    int n = (wy * 8 + iy) * 64 + wx * 8 + ix;
    return b * 4096 + n;
}

// ---------------- kernel 1: LN1 + window partition + q/k/v pre-LNs ---------
__global__ void k_prep(const float* __restrict__ x,
                       const float* __restrict__ g1, const float* __restrict__ b1,
                       const float* __restrict__ gq, const float* __restrict__ bq,
                       const float* __restrict__ gk, const float* __restrict__ bk,
                       const float* __restrict__ gv, const float* __restrict__ bv,
                       float* __restrict__ win, float* __restrict__ lnq,
                       float* __restrict__ lnk, float* __restrict__ lnv) {
    __shared__ float sm[8];
    int t = blockIdx.x;
    size_t src = (size_t)t_to_xrow(t) * CD;
    int tid = threadIdx.x;

    float xv[3], s = 0.f, sq = 0.f;
    #pragma unroll
    for (int j = 0; j < 3; j++) {
        float v = x[src + tid + j * 128];
        xv[j] = v; s += v; sq += v * v;
    }
    reduce2_128(s, sq, sm);
    float m = s * (1.f / CD);
    float r = rsqrtf(sq * (1.f / CD) - m * m + 1e-5f);

    float wv[3]; s = 0.f; sq = 0.f;
    #pragma unroll
    for (int j = 0; j < 3; j++) {
        int c = tid + j * 128;
        float v = (xv[j] - m) * r * g1[c] + b1[c];
        wv[j] = v; s += v; sq += v * v;
    }
    reduce2_128(s, sq, sm);
    float m2 = s * (1.f / CD);
    float r2 = rsqrtf(sq * (1.f / CD) - m2 * m2 + 1e-5f);

    size_t dst = (size_t)t * CD;
    #pragma unroll
    for (int j = 0; j < 3; j++) {
        int c = tid + j * 128;
        float v = wv[j];
        win[dst + c] = v;
        float u = (v - m2) * r2;
        lnq[dst + c] = u * gq[c] + bq[c];
        lnk[dst + c] = u * gk[c] + bk[c];
        lnv[dst + c] = u * gv[c] + bv[c];
    }
}

// ---------------- tiled fp32 GEMM: out = epi(A[M,K] @ W[N,K]^T + bias) -----
// EPI: 0 = bias only, 1 = bias + exact GELU, 2 = bias + residual add
template <int EPI>
__global__ void __launch_bounds__(256)
k_sgemm(const float* __restrict__ A, const float* __restrict__ Wt,
        const float* __restrict__ bias, const float* __restrict__ res,
        float* __restrict__ out, int M, int N, int K) {
    __shared__ float As[8][128];
    __shared__ float Bs[8][128];
    int tid = threadIdx.x;
    int tx = tid & 15, ty = tid >> 4;
    int bn = blockIdx.x, bm = blockIdx.y;

    float acc[8][8];
    #pragma unroll
    for (int i = 0; i < 8; i++)
        #pragma unroll
        for (int j = 0; j < 8; j++) acc[i][j] = 0.f;

    int lr = tid >> 1;
    int lc = (tid & 1) * 4;
    const float* Ap = A  + (size_t)(bm * 128 + lr) * K + lc;
    const float* Wp = Wt + (size_t)(bn * 128 + lr) * K + lc;

    for (int k0 = 0; k0 < K; k0 += 8) {
        float4 av = *(const float4*)(Ap + k0);
        float4 wv = *(const float4*)(Wp + k0);
        As[lc + 0][lr] = av.x; As[lc + 1][lr] = av.y;
        As[lc + 2][lr] = av.z; As[lc + 3][lr] = av.w;
        Bs[lc + 0][lr] = wv.x; Bs[lc + 1][lr] = wv.y;
        Bs[lc + 2][lr] = wv.z; Bs[lc + 3][lr] = wv.w;
        __syncthreads();
        #pragma unroll
        for (int kk = 0; kk < 8; kk++) {
            float ra[8], rb[8];
            #pragma unroll
            for (int i = 0; i < 8; i++) ra[i] = As[kk][ty * 8 + i];
            #pragma unroll
            for (int j = 0; j < 8; j++) rb[j] = Bs[kk][tx * 8 + j];
            #pragma unroll
            for (int i = 0; i < 8; i++)
                #pragma unroll
                for (int j = 0; j < 8; j++) acc[i][j] += ra[i] * rb[j];
        }
        __syncthreads();
    }

    #pragma unroll
    for (int i = 0; i < 8; i++) {
        int row = bm * 128 + ty * 8 + i;
        size_t rbase = (size_t)row * N;
        #pragma unroll
        for (int j = 0; j < 8; j++) {
            int col = bn * 128 + tx * 8 + j;
            float vv = acc[i][j] + bias[col];
            if (EPI == 1) vv = 0.5f * vv * (1.f + erff(vv * 0.70710678118654752f));
            if (EPI == 2) vv += res[rbase + col];
            out[rbase + col] = vv;
        }
    }
}

// ---------------- attention: one block per (window, head), 64 threads ------
__global__ void __launch_bounds__(64)
k_attn(const float* __restrict__ q, const float* __restrict__ k,
       const float* __restrict__ v, float* __restrict__ o) {
    __shared__ float Qs[64 * 33];
    __shared__ float Ks[64 * 32];
    __shared__ float Vs[64 * 32];
    int w = blockIdx.x, hd = blockIdx.y;
    int tid = threadIdx.x;
    size_t base = (size_t)w * 64 * CD + (size_t)hd * DHEAD;

    for (int i = tid; i < 64 * 32; i += 64) {
        int row = i >> 5, col = i & 31;
        size_t g = base + (size_t)row * CD + col;
        Qs[row * 33 + col] = q[g];
        Ks[i] = k[g];
        Vs[i] = v[g];
    }
    __syncthreads();

    float qr[32];
    #pragma unroll
    for (int d = 0; d < 32; d++) qr[d] = Qs[tid * 33 + d];

    const float scale = 0.17677669529663687f;  // 1/sqrt(32)
    float a[64];
    float mx = -1e30f;
    #pragma unroll
    for (int l = 0; l < 64; l++) {
        float s = 0.f;
        #pragma unroll
        for (int d = 0; d < 32; d++) s += qr[d] * Ks[l * 32 + d];
        s *= scale;
        a[l] = s;
        mx = fmaxf(mx, s);
    }
    float ssum = 0.f;
    #pragma unroll
    for (int l = 0; l < 64; l++) { float e = expf(a[l] - mx); a[l] = e; ssum += e; }
    float inv = 1.f / ssum;

    #pragma unroll
    for (int d = 0; d < 32; d++) {
        float acc = 0.f;
        #pragma unroll
        for (int l = 0; l < 64; l++) acc += a[l] * Vs[l * 32 + d];
        o[base + (size_t)tid * CD + d] = acc * inv;
    }
}

// ---------------- nout-LN + reverse-window + residual + LN2 ----------------
__global__ void k_lnout_ln2(const float* __restrict__ ores, const float* __restrict__ x,
                            const float* __restrict__ gno, const float* __restrict__ bno,
                            const float* __restrict__ g2,  const float* __restrict__ b2,
                            float* __restrict__ x2, float* __restrict__ ln2) {
    __shared__ float sm[8];
    int t = blockIdx.x;
    size_t src = (size_t)t * CD;                 // win layout
    size_t dst = (size_t)t_to_xrow(t) * CD;      // x layout
    int tid = threadIdx.x;

    float ov[3], s = 0.f, sq = 0.f;
    #pragma unroll
    for (int j = 0; j < 3; j++) {
        float v = ores[src + tid + j * 128];
        ov[j] = v; s += v; sq += v * v;
    }
    reduce2_128(s, sq, sm);
    float m = s * (1.f / CD);
    float r = rsqrtf(sq * (1.f / CD) - m * m + 1e-5f);

    float xv2[3]; s = 0.f; sq = 0.f;
    #pragma unroll
    for (int j = 0; j < 3; j++) {
        int c = tid + j * 128;
        float a = (ov[j] - m) * r * gno[c] + bno[c];
        float xx = x[dst + c] + a;
        xv2[j] = xx; s += xx; sq += xx * xx;
    }
    reduce2_128(s, sq, sm);
    float m2 = s * (1.f / CD);
    float r2 = rsqrtf(sq * (1.f / CD) - m2 * m2 + 1e-5f);

    #pragma unroll
    for (int j = 0; j < 3; j++) {
        int c = tid + j * 128;
        x2[dst + c]  = xv2[j];
        ln2[dst + c] = (xv2[j] - m2) * r2 * g2[c] + b2[c];
    }
}

// ---------------- host launcher --------------------------------------------
extern "C" void kernel_launch(void* const* d_in, const int* in_sizes, int n_in,
                              void* d_out, int out_size) {
    const float* x    = (const float*)d_in[0];
    const float* g1   = (const float*)d_in[1];
    const float* b1   = (const float*)d_in[2];
    const float* gq   = (const float*)d_in[3];
    const float* bq   = (const float*)d_in[4];
    const float* gk   = (const float*)d_in[5];
    const float* bk   = (const float*)d_in[6];
    const float* gv   = (const float*)d_in[7];
    const float* bv   = (const float*)d_in[8];
    const float* gno  = (const float*)d_in[9];
    const float* bno  = (const float*)d_in[10];
    const float* ipw  = (const float*)d_in[11];
    const float* ipb  = (const float*)d_in[12];
    const float* opw  = (const float*)d_in[13];
    const float* opb  = (const float*)d_in[14];
    const float* g2n  = (const float*)d_in[15];
    const float* b2n  = (const float*)d_in[16];
    const float* w1   = (const float*)d_in[17];
    const float* b1f  = (const float*)d_in[18];
    const float* w2   = (const float*)d_in[19];
    const float* b2f  = (const float*)d_in[20];
    // d_in[21] = H, d_in[22] = W (fixed at 64 by setup_inputs)

    int B = in_sizes[0] / (64 * 64 * CD);
    int T = B * 64 * 64;      // window-layout tokens == x tokens
    int nW = B * 64;          // number of 8x8 windows

    float *win, *lnq, *lnk, *lnv, *q, *k, *v, *h;
    cudaGetSymbolAddress((void**)&win, g_win);
    cudaGetSymbolAddress((void**)&lnq, g_lnq);
    cudaGetSymbolAddress((void**)&lnk, g_lnk);
    cudaGetSymbolAddress((void**)&lnv, g_lnv);
    cudaGetSymbolAddress((void**)&q,   g_q);
    cudaGetSymbolAddress((void**)&k,   g_k);
    cudaGetSymbolAddress((void**)&v,   g_v);
    cudaGetSymbolAddress((void**)&h,   g_h);

    // 1) LN1 + window partition + pre-LNs for q/k/v
    k_prep<<<T, 128>>>(x, g1, b1, gq, bq, gk, bk, gv, bv, win, lnq, lnk, lnv);

    // 2) QKV projections
    dim3 thr(256);
    dim3 gC(CD / 128, T / 128);
    k_sgemm<0><<<gC, thr>>>(lnq, ipw,               ipb,          nullptr, q, T, CD, CD);
    k_sgemm<0><<<gC, thr>>>(lnk, ipw + CD * CD,     ipb + CD,     nullptr, k, T, CD, CD);
    k_sgemm<0><<<gC, thr>>>(lnv, ipw + 2 * CD * CD, ipb + 2 * CD, nullptr, v, T, CD, CD);

    // 3) windowed attention -> o (reuse lnq)
    k_attn<<<dim3(nW, NHEAD), 64>>>(q, k, v, lnq);

    // 4) out_proj + residual(win) -> ores (reuse lnk)
    k_sgemm<2><<<gC, thr>>>(lnq, opw, opb, win, lnk, T, CD, CD);

    // 5) nout-LN + reverse window + x residual -> x2 (lnv), LN2 -> (q)
    k_lnout_ln2<<<T, 128>>>(lnk, x, gno, bno, g2n, b2n, lnv, q);

    // 6) MLP
    dim3 gF(FFD / 128, T / 128);
    k_sgemm<1><<<gF, thr>>>(q, w1, b1f, nullptr, h, T, FFD, CD);
    k_sgemm<2><<<gC, thr>>>(h, w2, b2f, lnv, (float*)d_out, T, CD, FFD);
}

// round 2
// speedup vs baseline: 2.6093x; 2.6093x over previous
#include <cuda_runtime.h>
#include <math.h>

#define CD 384
#define FFD 1536
#define NHEAD 12
#define DHEAD 32
#define TMAX (32*64*64)   // 131072 tokens (B=32 fixed by setup_inputs)

// ---------------- scratch (static device globals; no allocations) ----------
__device__ float g_win[(size_t)TMAX * CD];
__device__ float g_lnq[(size_t)TMAX * CD];
__device__ float g_lnk[(size_t)TMAX * CD];
__device__ float g_lnv[(size_t)TMAX * CD];
__device__ float g_q  [(size_t)TMAX * CD];
__device__ float g_k  [(size_t)TMAX * CD];
__device__ float g_v  [(size_t)TMAX * CD];
__device__ float g_h  [(size_t)TMAX * FFD];

// ---------------- block-wide (128 thr) sum of two values -------------------
__device__ __forceinline__ void reduce2_128(float& s0, float& s1, float* sm) {
    #pragma unroll
    for (int o = 16; o > 0; o >>= 1) {
        s0 += __shfl_down_sync(0xffffffffu, s0, o);
        s1 += __shfl_down_sync(0xffffffffu, s1, o);
    }
    int w = threadIdx.x >> 5;
    if ((threadIdx.x & 31) == 0) { sm[w] = s0; sm[4 + w] = s1; }
    __syncthreads();
    s0 = sm[0] + sm[1] + sm[2] + sm[3];
    s1 = sm[4] + sm[5] + sm[6] + sm[7];
    __syncthreads();
}

// win-layout token t -> x-layout flat row index
__device__ __forceinline__ int t_to_xrow(int t) {
    int w = t >> 6, l = t & 63;
    int b = w >> 6, wi = w & 63;
    int wy = wi >> 3, wx = wi & 7;
    int iy = l >> 3, ix = l & 7;
    int n = (wy * 8 + iy) * 64 + wx * 8 + ix;
    return b * 4096 + n;
}

// ---------------- kernel 1: LN1 + window partition + q/k/v pre-LNs ---------
__global__ void k_prep(const float* __restrict__ x,
                       const float* __restrict__ g1, const float* __restrict__ b1,
                       const float* __restrict__ gq, const float* __restrict__ bq,
                       const float* __restrict__ gk, const float* __restrict__ bk,
                       const float* __restrict__ gv, const float* __restrict__ bv,
                       float* __restrict__ win, float* __restrict__ lnq,
                       float* __restrict__ lnk, float* __restrict__ lnv) {
    __shared__ float sm[8];
    int t = blockIdx.x;
    size_t src = (size_t)t_to_xrow(t) * CD;
    int tid = threadIdx.x;

    float xv[3], s = 0.f, sq = 0.f;
    #pragma unroll
    for (int j = 0; j < 3; j++) {
        float v = x[src + tid + j * 128];
        xv[j] = v; s += v; sq += v * v;
    }
    reduce2_128(s, sq, sm);
    float m = s * (1.f / CD);
    float r = rsqrtf(sq * (1.f / CD) - m * m + 1e-5f);

    float wv[3]; s = 0.f; sq = 0.f;
    #pragma unroll
    for (int j = 0; j < 3; j++) {
        int c = tid + j * 128;
        float v = (xv[j] - m) * r * g1[c] + b1[c];
        wv[j] = v; s += v; sq += v * v;
    }
    reduce2_128(s, sq, sm);
    float m2 = s * (1.f / CD);
    float r2 = rsqrtf(sq * (1.f / CD) - m2 * m2 + 1e-5f);

    size_t dst = (size_t)t * CD;
    #pragma unroll
    for (int j = 0; j < 3; j++) {
        int c = tid + j * 128;
        float v = wv[j];
        win[dst + c] = v;
        float u = (v - m2) * r2;
        lnq[dst + c] = u * gq[c] + bq[c];
        lnk[dst + c] = u * gk[c] + bk[c];
        lnv[dst + c] = u * gv[c] + bv[c];
    }
}

// ---------------- tf32 tensor-core GEMM ------------------------------------
// out[M,N] = epi(A[M,K] @ Wt[N,K]^T + bias)
// EPI: 0 = bias only, 1 = bias + exact GELU, 2 = bias + residual add
__device__ __forceinline__ unsigned f2tf(float f) {
    unsigned u;
    asm("cvt.rna.tf32.f32 %0, %1;" : "=r"(u) : "f"(f));
    return u;
}

template <int EPI>
__global__ void __launch_bounds__(256)
k_mma(const float* __restrict__ A, const float* __restrict__ Wt,
      const float* __restrict__ bias, const float* __restrict__ res,
      float* __restrict__ out, int M, int N, int K) {
    __shared__ unsigned As[128][20];   // [m][k], pad 16->20 (conflict-free)
    __shared__ unsigned Bs[128][20];   // [n][k]
    int tid  = threadIdx.x;
    int lane = tid & 31, warp = tid >> 5;
    int wm = warp >> 2, wn = warp & 3;        // 2 x 4 warp grid (64x32 per warp)
    int gid = lane >> 2, tg = lane & 3;
    int bn = blockIdx.x, bm = blockIdx.y;

    float acc[4][4][4];
    #pragma unroll
    for (int i = 0; i < 4; i++)
        #pragma unroll
        for (int j = 0; j < 4; j++)
            #pragma unroll
            for (int r = 0; r < 4; r++) acc[i][j][r] = 0.f;

    int r0 = tid >> 2;                 // 0..63
    int c4 = (tid & 3) * 4;            // 0,4,8,12
    const float* Ap0 = A  + (size_t)(bm * 128 + r0) * K + c4;
    const float* Ap1 = A  + (size_t)(bm * 128 + r0 + 64) * K + c4;
    const float* Bp0 = Wt + (size_t)(bn * 128 + r0) * K + c4;
    const float* Bp1 = Wt + (size_t)(bn * 128 + r0 + 64) * K + c4;

    for (int k0 = 0; k0 < K; k0 += 16) {
        float4 av0 = *(const float4*)(Ap0 + k0);
        float4 av1 = *(const float4*)(Ap1 + k0);
        float4 bv0 = *(const float4*)(Bp0 + k0);
        float4 bv1 = *(const float4*)(Bp1 + k0);
        __syncthreads();   // previous iter's compute done before overwrite
        {
            uint4 u;
            u.x = f2tf(av0.x); u.y = f2tf(av0.y); u.z = f2tf(av0.z); u.w = f2tf(av0.w);
            *(uint4*)&As[r0][c4] = u;
            u.x = f2tf(av1.x); u.y = f2tf(av1.y); u.z = f2tf(av1.z); u.w = f2tf(av1.w);
            *(uint4*)&As[r0 + 64][c4] = u;
            u.x = f2tf(bv0.x); u.y = f2tf(bv0.y); u.z = f2tf(bv0.z); u.w = f2tf(bv0.w);
            *(uint4*)&Bs[r0][c4] = u;
            u.x = f2tf(bv1.x); u.y = f2tf(bv1.y); u.z = f2tf(bv1.z); u.w = f2tf(bv1.w);
            *(uint4*)&Bs[r0 + 64][c4] = u;
        }
        __syncthreads();

        #pragma unroll
        for (int ks = 0; ks < 2; ks++) {
            int kk = ks * 8 + tg;
            unsigned af[4][4], bf[4][2];
            #pragma unroll
            for (int mt = 0; mt < 4; mt++) {
                int rr = wm * 64 + mt * 16 + gid;
                af[mt][0] = As[rr][kk];
                af[mt][1] = As[rr + 8][kk];
                af[mt][2] = As[rr][kk + 4];
                af[mt][3] = As[rr + 8][kk + 4];
            }
            #pragma unroll
            for (int nt = 0; nt < 4; nt++) {
                int cc = wn * 32 + nt * 8 + gid;
                bf[nt][0] = Bs[cc][kk];
                bf[nt][1] = Bs[cc][kk + 4];
            }
            #pragma unroll
            for (int mt = 0; mt < 4; mt++)
                #pragma unroll
                for (int nt = 0; nt < 4; nt++) {
                    asm volatile(
                        "mma.sync.aligned.m16n8k8.row.col.f32.tf32.tf32.f32 "
                        "{%0,%1,%2,%3}, {%4,%5,%6,%7}, {%8,%9}, {%0,%1,%2,%3};"
                        : "+f"(acc[mt][nt][0]), "+f"(acc[mt][nt][1]),
                          "+f"(acc[mt][nt][2]), "+f"(acc[mt][nt][3])
                        : "r"(af[mt][0]), "r"(af[mt][1]), "r"(af[mt][2]), "r"(af[mt][3]),
                          "r"(bf[nt][0]), "r"(bf[nt][1]));
                }
        }
    }

    // epilogue
    #pragma unroll
    for (int mt = 0; mt < 4; mt++) {
        int row0 = bm * 128 + wm * 64 + mt * 16 + gid;
        #pragma unroll
        for (int nt = 0; nt < 4; nt++) {
            int col = bn * 128 + wn * 32 + nt * 8 + tg * 2;
            float bi0 = bias[col], bi1 = bias[col + 1];
            #pragma unroll
            for (int h = 0; h < 2; h++) {
                int row = row0 + h * 8;
                size_t off = (size_t)row * N + col;
                float v0 = acc[mt][nt][h * 2 + 0] + bi0;
                float v1 = acc[mt][nt][h * 2 + 1] + bi1;
                if (EPI == 1) {
                    v0 = 0.5f * v0 * (1.f + erff(v0 * 0.70710678118654752f));
                    v1 = 0.5f * v1 * (1.f + erff(v1 * 0.70710678118654752f));
                }
                if (EPI == 2) {
                    float2 rr = *(const float2*)(res + off);
                    v0 += rr.x; v1 += rr.y;
                }
                float2 ov; ov.x = v0; ov.y = v1;
                *(float2*)(out + off) = ov;
            }
        }
    }
}

// ---------------- attention: one block per (window, head), 64 threads ------
__global__ void __launch_bounds__(64)
k_attn(const float* __restrict__ q, const float* __restrict__ k,
       const float* __restrict__ v, float* __restrict__ o) {
    __shared__ float Qs[64 * 33];
    __shared__ float Ks[64 * 32];
    __shared__ float Vs[64 * 32];
    int w = blockIdx.x, hd = blockIdx.y;
    int tid = threadIdx.x;
    size_t base = (size_t)w * 64 * CD + (size_t)hd * DHEAD;

    for (int i = tid; i < 64 * 32; i += 64) {
        int row = i >> 5, col = i & 31;
        size_t g = base + (size_t)row * CD + col;
        Qs[row * 33 + col] = q[g];
        Ks[i] = k[g];
        Vs[i] = v[g];
    }
    __syncthreads();

    float qr[32];
    #pragma unroll
    for (int d = 0; d < 32; d++) qr[d] = Qs[tid * 33 + d];

    const float scale = 0.17677669529663687f;  // 1/sqrt(32)
    float a[64];
    float mx = -1e30f;
    #pragma unroll
    for (int l = 0; l < 64; l++) {
        float s = 0.f;
        #pragma unroll
        for (int d = 0; d < 32; d++) s += qr[d] * Ks[l * 32 + d];
        s *= scale;
        a[l] = s;
        mx = fmaxf(mx, s);
    }
    float ssum = 0.f;
    #pragma unroll
    for (int l = 0; l < 64; l++) { float e = expf(a[l] - mx); a[l] = e; ssum += e; }
    float inv = 1.f / ssum;

    #pragma unroll
    for (int d = 0; d < 32; d++) {
        float acc = 0.f;
        #pragma unroll
        for (int l = 0; l < 64; l++) acc += a[l] * Vs[l * 32 + d];
        o[base + (size_t)tid * CD + d] = acc * inv;
    }
}

// ---------------- nout-LN + reverse-window + residual + LN2 ----------------
__global__ void k_lnout_ln2(const float* __restrict__ ores, const float* __restrict__ x,
                            const float* __restrict__ gno, const float* __restrict__ bno,
                            const float* __restrict__ g2,  const float* __restrict__ b2,
                            float* __restrict__ x2, float* __restrict__ ln2) {
    __shared__ float sm[8];
    int t = blockIdx.x;
    size_t src = (size_t)t * CD;                 // win layout
    size_t dst = (size_t)t_to_xrow(t) * CD;      // x layout
    int tid = threadIdx.x;

    float ov[3], s = 0.f, sq = 0.f;
    #pragma unroll
    for (int j = 0; j < 3; j++) {
        float v = ores[src + tid + j * 128];
        ov[j] = v; s += v; sq += v * v;
    }
    reduce2_128(s, sq, sm);
    float m = s * (1.f / CD);
    float r = rsqrtf(sq * (1.f / CD) - m * m + 1e-5f);

    float xv2[3]; s = 0.f; sq = 0.f;
    #pragma unroll
    for (int j = 0; j < 3; j++) {
        int c = tid + j * 128;
        float a = (ov[j] - m) * r * gno[c] + bno[c];
        float xx = x[dst + c] + a;
        xv2[j] = xx; s += xx; sq += xx * xx;
    }
    reduce2_128(s, sq, sm);
    float m2 = s * (1.f / CD);
    float r2 = rsqrtf(sq * (1.f / CD) - m2 * m2 + 1e-5f);

    #pragma unroll
    for (int j = 0; j < 3; j++) {
        int c = tid + j * 128;
        x2[dst + c]  = xv2[j];
        ln2[dst + c] = (xv2[j] - m2) * r2 * g2[c] + b2[c];
    }
}

// ---------------- host launcher --------------------------------------------
extern "C" void kernel_launch(void* const* d_in, const int* in_sizes, int n_in,
                              void* d_out, int out_size) {
    const float* x    = (const float*)d_in[0];
    const float* g1   = (const float*)d_in[1];
    const float* b1   = (const float*)d_in[2];
    const float* gq   = (const float*)d_in[3];
    const float* bq   = (const float*)d_in[4];
    const float* gk   = (const float*)d_in[5];
    const float* bk   = (const float*)d_in[6];
    const float* gv   = (const float*)d_in[7];
    const float* bv   = (const float*)d_in[8];
    const float* gno  = (const float*)d_in[9];
    const float* bno  = (const float*)d_in[10];
    const float* ipw  = (const float*)d_in[11];
    const float* ipb  = (const float*)d_in[12];
    const float* opw  = (const float*)d_in[13];
    const float* opb  = (const float*)d_in[14];
    const float* g2n  = (const float*)d_in[15];
    const float* b2n  = (const float*)d_in[16];
    const float* w1   = (const float*)d_in[17];
    const float* b1f  = (const float*)d_in[18];
    const float* w2   = (const float*)d_in[19];
    const float* b2f  = (const float*)d_in[20];

    int B = in_sizes[0] / (64 * 64 * CD);
    int T = B * 64 * 64;      // tokens
    int nW = B * 64;          // number of 8x8 windows

    float *win, *lnq, *lnk, *lnv, *q, *k, *v, *h;
    cudaGetSymbolAddress((void**)&win, g_win);
    cudaGetSymbolAddress((void**)&lnq, g_lnq);
    cudaGetSymbolAddress((void**)&lnk, g_lnk);
    cudaGetSymbolAddress((void**)&lnv, g_lnv);
    cudaGetSymbolAddress((void**)&q,   g_q);
    cudaGetSymbolAddress((void**)&k,   g_k);
    cudaGetSymbolAddress((void**)&v,   g_v);
    cudaGetSymbolAddress((void**)&h,   g_h);

    // 1) LN1 + window partition + pre-LNs for q/k/v
    k_prep<<<T, 128>>>(x, g1, b1, gq, bq, gk, bk, gv, bv, win, lnq, lnk, lnv);

    // 2) QKV projections (tf32 tensor cores)
    dim3 thr(256);
    dim3 gC(CD / 128, T / 128);
    k_mma<0><<<gC, thr>>>(lnq, ipw,               ipb,          nullptr, q, T, CD, CD);
    k_mma<0><<<gC, thr>>>(lnk, ipw + CD * CD,     ipb + CD,     nullptr, k, T, CD, CD);
    k_mma<0><<<gC, thr>>>(lnv, ipw + 2 * CD * CD, ipb + 2 * CD, nullptr, v, T, CD, CD);

    // 3) windowed attention -> o (reuse lnq)
    k_attn<<<dim3(nW, NHEAD), 64>>>(q, k, v, lnq);

    // 4) out_proj + residual(win) -> ores (reuse lnk)
    k_mma<2><<<gC, thr>>>(lnq, opw, opb, win, lnk, T, CD, CD);

    // 5) nout-LN + reverse window + x residual -> x2 (lnv), LN2 -> (q)
    k_lnout_ln2<<<T, 128>>>(lnk, x, gno, bno, g2n, b2n, lnv, q);

    // 6) MLP (tf32 tensor cores)
    dim3 gF(FFD / 128, T / 128);
    k_mma<1><<<gF, thr>>>(q, w1, b1f, nullptr, h, T, FFD, CD);
    k_mma<2><<<gC, thr>>>(h, w2, b2f, lnv, (float*)d_out, T, CD, FFD);
}

// round 3
// speedup vs baseline: 4.0089x; 1.5364x over previous
#include <cuda_runtime.h>
#include <cuda_bf16.h>
#include <math.h>

#define CD 384
#define FFD 1536
#define NHEAD 12
#define DHEAD 32
#define TMAX (32*64*64)   // 131072 tokens (B=32 fixed by setup_inputs)

typedef __nv_bfloat16 bf16;

// ---------------- scratch (static device globals; no allocations) ----------
__device__ float g_win[(size_t)TMAX * CD];
__device__ float g_q  [(size_t)TMAX * CD];
__device__ float g_k  [(size_t)TMAX * CD];
__device__ float g_v  [(size_t)TMAX * CD];
__device__ bf16  g_lnq[(size_t)TMAX * CD];
__device__ bf16  g_lnk[(size_t)TMAX * CD];
__device__ bf16  g_lnv[(size_t)TMAX * CD];
__device__ bf16  g_obf[(size_t)TMAX * CD];
__device__ bf16  g_ln2[(size_t)TMAX * CD];
__device__ bf16  g_hbf[(size_t)TMAX * FFD];
#define W_IPW 0
#define W_OPW (3*CD*CD)
#define W_W1  (W_OPW + CD*CD)
#define W_W2  (W_W1 + FFD*CD)
#define W_TOT (W_W2 + CD*FFD)
__device__ bf16  g_wbf[W_TOT];

// ---------------- fp32 -> bf16 conversion ---------------------------------
__global__ void k_f2bf(const float* __restrict__ src, bf16* __restrict__ dst, int n) {
    int i = blockIdx.x * blockDim.x + threadIdx.x;
    if (i < n) dst[i] = __float2bfloat16(src[i]);
}

// ---------------- block-wide (128 thr) sum of two values -------------------
__device__ __forceinline__ void reduce2_128(float& s0, float& s1, float* sm) {
    #pragma unroll
    for (int o = 16; o > 0; o >>= 1) {
        s0 += __shfl_down_sync(0xffffffffu, s0, o);
        s1 += __shfl_down_sync(0xffffffffu, s1, o);
    }
    int w = threadIdx.x >> 5;
    if ((threadIdx.x & 31) == 0) { sm[w] = s0; sm[4 + w] = s1; }
    __syncthreads();
    s0 = sm[0] + sm[1] + sm[2] + sm[3];
    s1 = sm[4] + sm[5] + sm[6] + sm[7];
    __syncthreads();
}

// win-layout token t -> x-layout flat row index
__device__ __forceinline__ int t_to_xrow(int t) {
    int w = t >> 6, l = t & 63;
    int b = w >> 6, wi = w & 63;
    int wy = wi >> 3, wx = wi & 7;
    int iy = l >> 3, ix = l & 7;
    int n = (wy * 8 + iy) * 64 + wx * 8 + ix;
    return b * 4096 + n;
}

// ---------------- kernel 1: LN1 + window partition + q/k/v pre-LNs ---------
__global__ void k_prep(const float* __restrict__ x,
                       const float* __restrict__ g1, const float* __restrict__ b1,
                       const float* __restrict__ gq, const float* __restrict__ bq,
                       const float* __restrict__ gk, const float* __restrict__ bk,
                       const float* __restrict__ gv, const float* __restrict__ bv,
                       float* __restrict__ win, bf16* __restrict__ lnq,
                       bf16* __restrict__ lnk, bf16* __restrict__ lnv) {
    __shared__ float sm[8];
    int t = blockIdx.x;
    size_t src = (size_t)t_to_xrow(t) * CD;
    int tid = threadIdx.x;

    float xv[3], s = 0.f, sq = 0.f;
    #pragma unroll
    for (int j = 0; j < 3; j++) {
        float v = x[src + tid + j * 128];
        xv[j] = v; s += v; sq += v * v;
    }
    reduce2_128(s, sq, sm);
    float m = s * (1.f / CD);
    float r = rsqrtf(sq * (1.f / CD) - m * m + 1e-5f);

    float wv[3]; s = 0.f; sq = 0.f;
    #pragma unroll
    for (int j = 0; j < 3; j++) {
        int c = tid + j * 128;
        float v = (xv[j] - m) * r * g1[c] + b1[c];
        wv[j] = v; s += v; sq += v * v;
    }
    reduce2_128(s, sq, sm);
    float m2 = s * (1.f / CD);
    float r2 = rsqrtf(sq * (1.f / CD) - m2 * m2 + 1e-5f);

    size_t dst = (size_t)t * CD;
    #pragma unroll
    for (int j = 0; j < 3; j++) {
        int c = tid + j * 128;
        float v = wv[j];
        win[dst + c] = v;
        float u = (v - m2) * r2;
        lnq[dst + c] = __float2bfloat16(u * gq[c] + bq[c]);
        lnk[dst + c] = __float2bfloat16(u * gk[c] + bk[c]);
        lnv[dst + c] = __float2bfloat16(u * gv[c] + bv[c]);
    }
}

// ---------------- bf16 tensor-core GEMM with cp.async pipeline -------------
// out[M,N] = epi(A[M,K] @ Wt[N,K]^T + bias)
// EPI: 0 = bias only (f32 out), 1 = bias + GELU (bf16 out), 2 = bias + res (f32 out)
__device__ __forceinline__ void cpa16(void* dst, const void* src) {
    unsigned d = (unsigned)__cvta_generic_to_shared(dst);
    asm volatile("cp.async.cg.shared.global [%0], [%1], 16;" :: "r"(d), "l"(src));
}

template <int EPI>
__global__ void __launch_bounds__(256, 2)
k_mma(const bf16* __restrict__ A, const bf16* __restrict__ Wt,
      const float* __restrict__ bias, const float* __restrict__ res,
      void* __restrict__ outv, int M, int N, int K) {
    __shared__ bf16 As[2][128][40];   // [stage][m][k], k-chunk 32 pad->40
    __shared__ bf16 Bs[2][128][40];
    int tid  = threadIdx.x;
    int lane = tid & 31, warp = tid >> 5;
    int wm = warp >> 2, wn = warp & 3;        // 2 x 4 warp grid (64x32 per warp)
    int gid = lane >> 2, tg = lane & 3;
    int bn = blockIdx.x, bm = blockIdx.y;

    const bf16* Ab = A  + (size_t)bm * 128 * K;
    const bf16* Bb = Wt + (size_t)bn * 128 * K;

    float acc[4][4][4];
    #pragma unroll
    for (int i = 0; i < 4; i++)
        #pragma unroll
        for (int j = 0; j < 4; j++)
            #pragma unroll
            for (int r = 0; r < 4; r++) acc[i][j][r] = 0.f;

    // prologue: stage 0
    #pragma unroll
    for (int j = 0; j < 2; j++) {
        int idx = tid * 2 + j, row = idx >> 2, c = idx & 3;
        cpa16(&As[0][row][c * 8], Ab + (size_t)row * K + c * 8);
        cpa16(&Bs[0][row][c * 8], Bb + (size_t)row * K + c * 8);
    }
    asm volatile("cp.async.commit_group;");

    int nstg = K >> 5;
    for (int st = 0; st < nstg; st++) {
        int s = st & 1;
        if (st + 1 < nstg) {
            int k0 = (st + 1) << 5;
            #pragma unroll
            for (int j = 0; j < 2; j++) {
                int idx = tid * 2 + j, row = idx >> 2, c = idx & 3;
                cpa16(&As[s ^ 1][row][c * 8], Ab + (size_t)row * K + k0 + c * 8);
                cpa16(&Bs[s ^ 1][row][c * 8], Bb + (size_t)row * K + k0 + c * 8);
            }
            asm volatile("cp.async.commit_group;");
            asm volatile("cp.async.wait_group 1;");
        } else {
            asm volatile("cp.async.wait_group 0;");
        }
        __syncthreads();

        #pragma unroll
        for (int ks = 0; ks < 2; ks++) {
            int kk = ks * 16;
            unsigned af[4][4], bfr[4][2];
            #pragma unroll
            for (int mt = 0; mt < 4; mt++) {
                int rr = wm * 64 + mt * 16 + gid;
                af[mt][0] = *(const unsigned*)&As[s][rr][kk + 2 * tg];
                af[mt][1] = *(const unsigned*)&As[s][rr + 8][kk + 2 * tg];
                af[mt][2] = *(const unsigned*)&As[s][rr][kk + 8 + 2 * tg];
                af[mt][3] = *(const unsigned*)&As[s][rr + 8][kk + 8 + 2 * tg];
            }
            #pragma unroll
            for (int nt = 0; nt < 4; nt++) {
                int cc = wn * 32 + nt * 8 + gid;
                bfr[nt][0] = *(const unsigned*)&Bs[s][cc][kk + 2 * tg];
                bfr[nt][1] = *(const unsigned*)&Bs[s][cc][kk + 8 + 2 * tg];
            }
            #pragma unroll
            for (int mt = 0; mt < 4; mt++)
                #pragma unroll
                for (int nt = 0; nt < 4; nt++) {
                    asm volatile(
                        "mma.sync.aligned.m16n8k16.row.col.f32.bf16.bf16.f32 "
                        "{%0,%1,%2,%3}, {%4,%5,%6,%7}, {%8,%9}, {%0,%1,%2,%3};"
                        : "+f"(acc[mt][nt][0]), "+f"(acc[mt][nt][1]),
                          "+f"(acc[mt][nt][2]), "+f"(acc[mt][nt][3])
                        : "r"(af[mt][0]), "r"(af[mt][1]), "r"(af[mt][2]), "r"(af[mt][3]),
                          "r"(bfr[nt][0]), "r"(bfr[nt][1]));
                }
        }
        __syncthreads();
    }

    // epilogue
    float* outf = (float*)outv;
    bf16*  outb = (bf16*)outv;
    #pragma unroll
    for (int mt = 0; mt < 4; mt++) {
        int row0 = bm * 128 + wm * 64 + mt * 16 + gid;
        #pragma unroll
        for (int nt = 0; nt < 4; nt++) {
            int col = bn * 128 + wn * 32 + nt * 8 + tg * 2;
            float bi0 = bias[col], bi1 = bias[col + 1];
            #pragma unroll
            for (int h = 0; h < 2; h++) {
                int row = row0 + h * 8;
                size_t off = (size_t)row * N + col;
                float v0 = acc[mt][nt][h * 2 + 0] + bi0;
                float v1 = acc[mt][nt][h * 2 + 1] + bi1;
                if (EPI == 1) {
                    v0 = 0.5f * v0 * (1.f + erff(v0 * 0.70710678118654752f));
                    v1 = 0.5f * v1 * (1.f + erff(v1 * 0.70710678118654752f));
                    __nv_bfloat162 ob;
                    ob.x = __float2bfloat16(v0); ob.y = __float2bfloat16(v1);
                    *(__nv_bfloat162*)(outb + off) = ob;
                } else {
                    if (EPI == 2) {
                        float2 rr = *(const float2*)(res + off);
                        v0 += rr.x; v1 += rr.y;
                    }
                    float2 ov; ov.x = v0; ov.y = v1;
                    *(float2*)(outf + off) = ov;
                }
            }
        }
    }
}

// ---------------- attention: one block per (window, head), 64 threads ------
__global__ void __launch_bounds__(64)
k_attn(const float* __restrict__ q, const float* __restrict__ k,
       const float* __restrict__ v, bf16* __restrict__ o) {
    __shared__ float Qs[64 * 33];
    __shared__ float Ks[64 * 32];
    __shared__ float Vs[64 * 32];
    int w = blockIdx.x, hd = blockIdx.y;
    int tid = threadIdx.x;
    size_t base = (size_t)w * 64 * CD + (size_t)hd * DHEAD;

    for (int i = tid; i < 64 * 32; i += 64) {
        int row = i >> 5, col = i & 31;
        size_t g = base + (size_t)row * CD + col;
        Qs[row * 33 + col] = q[g];
        Ks[i] = k[g];
        Vs[i] = v[g];
    }
    __syncthreads();

    float qr[32];
    #pragma unroll
    for (int d = 0; d < 32; d++) qr[d] = Qs[tid * 33 + d];

    const float scale = 0.17677669529663687f;  // 1/sqrt(32)
    float a[64];
    float mx = -1e30f;
    #pragma unroll
    for (int l = 0; l < 64; l++) {
        float s = 0.f;
        #pragma unroll
        for (int d = 0; d < 32; d++) s += qr[d] * Ks[l * 32 + d];
        s *= scale;
        a[l] = s;
        mx = fmaxf(mx, s);
    }
    float ssum = 0.f;
    #pragma unroll
    for (int l = 0; l < 64; l++) { float e = expf(a[l] - mx); a[l] = e; ssum += e; }
    float inv = 1.f / ssum;

    #pragma unroll
    for (int d = 0; d < 32; d++) {
        float acc = 0.f;
        #pragma unroll
        for (int l = 0; l < 64; l++) acc += a[l] * Vs[l * 32 + d];
        o[base + (size_t)tid * CD + d] = __float2bfloat16(acc * inv);
    }
}

// ---------------- nout-LN + reverse-window + residual + LN2 ----------------
__global__ void k_lnout_ln2(const float* __restrict__ ores, const float* __restrict__ x,
                            const float* __restrict__ gno, const float* __restrict__ bno,
                            const float* __restrict__ g2,  const float* __restrict__ b2,
                            float* __restrict__ x2, bf16* __restrict__ ln2) {
    __shared__ float sm[8];
    int t = blockIdx.x;
    size_t src = (size_t)t * CD;                 // win layout
    size_t dst = (size_t)t_to_xrow(t) * CD;      // x layout
    int tid = threadIdx.x;

    float ov[3], s = 0.f, sq = 0.f;
    #pragma unroll
    for (int j = 0; j < 3; j++) {
        float v = ores[src + tid + j * 128];
        ov[j] = v; s += v; sq += v * v;
    }
    reduce2_128(s, sq, sm);
    float m = s * (1.f / CD);
    float r = rsqrtf(sq * (1.f / CD) - m * m + 1e-5f);

    float xv2[3]; s = 0.f; sq = 0.f;
    #pragma unroll
    for (int j = 0; j < 3; j++) {
        int c = tid + j * 128;
        float a = (ov[j] - m) * r * gno[c] + bno[c];
        float xx = x[dst + c] + a;
        xv2[j] = xx; s += xx; sq += xx * xx;
    }
    reduce2_128(s, sq, sm);
    float m2 = s * (1.f / CD);
    float r2 = rsqrtf(sq * (1.f / CD) - m2 * m2 + 1e-5f);

    #pragma unroll
    for (int j = 0; j < 3; j++) {
        int c = tid + j * 128;
        x2[dst + c]  = xv2[j];
        ln2[dst + c] = __float2bfloat16((xv2[j] - m2) * r2 * g2[c] + b2[c]);
    }
}

// ---------------- host launcher --------------------------------------------
extern "C" void kernel_launch(void* const* d_in, const int* in_sizes, int n_in,
                              void* d_out, int out_size) {
    const float* x    = (const float*)d_in[0];
    const float* g1   = (const float*)d_in[1];
    const float* b1   = (const float*)d_in[2];
    const float* gq   = (const float*)d_in[3];
    const float* bq   = (const float*)d_in[4];
    const float* gk   = (const float*)d_in[5];
    const float* bk   = (const float*)d_in[6];
    const float* gv   = (const float*)d_in[7];
    const float* bv   = (const float*)d_in[8];
    const float* gno  = (const float*)d_in[9];
    const float* bno  = (const float*)d_in[10];
    const float* ipw  = (const float*)d_in[11];
    const float* ipb  = (const float*)d_in[12];
    const float* opw  = (const float*)d_in[13];
    const float* opb  = (const float*)d_in[14];
    const float* g2n  = (const float*)d_in[15];
    const float* b2n  = (const float*)d_in[16];
    const float* w1   = (const float*)d_in[17];
    const float* b1f  = (const float*)d_in[18];
    const float* w2   = (const float*)d_in[19];
    const float* b2f  = (const float*)d_in[20];

    int B = in_sizes[0] / (64 * 64 * CD);
    int T = B * 64 * 64;      // tokens
    int nW = B * 64;          // number of 8x8 windows

    float *win, *q, *k, *v;
    bf16 *lnq, *lnk, *lnv, *obf, *ln2, *hbf, *wbf;
    cudaGetSymbolAddress((void**)&win, g_win);
    cudaGetSymbolAddress((void**)&q,   g_q);
    cudaGetSymbolAddress((void**)&k,   g_k);
    cudaGetSymbolAddress((void**)&v,   g_v);
    cudaGetSymbolAddress((void**)&lnq, g_lnq);
    cudaGetSymbolAddress((void**)&lnk, g_lnk);
    cudaGetSymbolAddress((void**)&lnv, g_lnv);
    cudaGetSymbolAddress((void**)&obf, g_obf);
    cudaGetSymbolAddress((void**)&ln2, g_ln2);
    cudaGetSymbolAddress((void**)&hbf, g_hbf);
    cudaGetSymbolAddress((void**)&wbf, g_wbf);

    // 0) weights -> bf16 (small)
    k_f2bf<<<(3*CD*CD + 255) / 256, 256>>>(ipw, wbf + W_IPW, 3*CD*CD);
    k_f2bf<<<(CD*CD   + 255) / 256, 256>>>(opw, wbf + W_OPW, CD*CD);
    k_f2bf<<<(FFD*CD  + 255) / 256, 256>>>(w1,  wbf + W_W1,  FFD*CD);
    k_f2bf<<<(CD*FFD  + 255) / 256, 256>>>(w2,  wbf + W_W2,  CD*FFD);

    // 1) LN1 + window partition + pre-LNs for q/k/v (bf16 outputs)
    k_prep<<<T, 128>>>(x, g1, b1, gq, bq, gk, bk, gv, bv, win, lnq, lnk, lnv);

    // 2) QKV projections (bf16 tensor cores, f32 out)
    dim3 thr(256);
    dim3 gC(CD / 128, T / 128);
    k_mma<0><<<gC, thr>>>(lnq, wbf + W_IPW,             ipb,          nullptr, q, T, CD, CD);
    k_mma<0><<<gC, thr>>>(lnk, wbf + W_IPW + CD*CD,     ipb + CD,     nullptr, k, T, CD, CD);
    k_mma<0><<<gC, thr>>>(lnv, wbf + W_IPW + 2*CD*CD,   ipb + 2*CD,   nullptr, v, T, CD, CD);

    // 3) windowed attention -> obf (bf16)
    k_attn<<<dim3(nW, NHEAD), 64>>>(q, k, v, obf);

    // 4) out_proj + residual(win) -> ores (reuse q, f32)
    k_mma<2><<<gC, thr>>>(obf, wbf + W_OPW, opb, win, q, T, CD, CD);

    // 5) nout-LN + reverse window + x residual -> x2 (reuse k, f32), LN2 -> ln2 (bf16)
    k_lnout_ln2<<<T, 128>>>(q, x, gno, bno, g2n, b2n, k, ln2);

    // 6) MLP: ln2 @ w1 + gelu -> hbf (bf16), hbf @ w2 + x2 -> d_out (f32)
    dim3 gF(FFD / 128, T / 128);
    k_mma<1><<<gF, thr>>>(ln2, wbf + W_W1, b1f, nullptr, hbf, T, FFD, CD);
    k_mma<2><<<gC, thr>>>(hbf, wbf + W_W2, b2f, k, (float*)d_out, T, CD, FFD);
}

// round 4
// speedup vs baseline: 5.2912x; 1.3199x over previous
#include <cuda_runtime.h>
#include <cuda_bf16.h>
#include <math.h>

#define CD 384
#define FFD 1536
#define NQKV 1152
#define NHEAD 12
#define DHEAD 32
#define TMAX (32*64*64)

typedef __nv_bfloat16 bf16;

// ---------------- scratch ----------------
__device__ float g_win [(size_t)TMAX * CD];
__device__ bf16  g_u   [(size_t)TMAX * CD];
__device__ bf16  g_qkv [(size_t)TMAX * NQKV];
__device__ bf16  g_obf [(size_t)TMAX * CD];
__device__ float g_ores[(size_t)TMAX * CD];
__device__ float g_x2  [(size_t)TMAX * CD];
__device__ bf16  g_u2  [(size_t)TMAX * CD];
__device__ bf16  g_hbf [(size_t)TMAX * FFD];
__device__ bf16  g_wqkv[NQKV * CD];
__device__ float g_bqkv[NQKV];
__device__ bf16  g_opw [CD * CD];
__device__ bf16  g_w1  [FFD * CD];
__device__ float g_b1p [FFD];
__device__ bf16  g_w2  [CD * FFD];

// ---------------- small helpers ----------------
__global__ void k_f2bf(const float* __restrict__ s, bf16* __restrict__ d, int n) {
    int i = blockIdx.x * blockDim.x + threadIdx.x;
    if (i < n) d[i] = __float2bfloat16(s[i]);
}

// fold pre-LN affine (g,b) + optional scale into W (row n) and bias
__global__ void k_wqkv(const float* __restrict__ ipw, const float* __restrict__ ipb,
                       const float* __restrict__ gq, const float* __restrict__ bq,
                       const float* __restrict__ gk, const float* __restrict__ bk,
                       const float* __restrict__ gv, const float* __restrict__ bv,
                       bf16* __restrict__ Wo, float* __restrict__ bo) {
    __shared__ float sm[4];
    int n = blockIdx.x, tid = threadIdx.x;
    int s = n / CD;
    const float* g = (s == 0) ? gq : (s == 1) ? gk : gv;
    const float* bb = (s == 0) ? bq : (s == 1) ? bk : bv;
    float scl = (s == 0) ? 0.17677669529663687f : 1.f;   // 1/sqrt(32) folded into Q
    float part = 0.f;
    for (int c = tid; c < CD; c += 128) {
        float wv = ipw[(size_t)n * CD + c];
        part += wv * bb[c];
        Wo[(size_t)n * CD + c] = __float2bfloat16(wv * g[c] * scl);
    }
    #pragma unroll
    for (int o = 16; o > 0; o >>= 1) part += __shfl_down_sync(0xffffffffu, part, o);
    if ((tid & 31) == 0) sm[tid >> 5] = part;
    __syncthreads();
    if (tid == 0) bo[n] = (ipb[n] + sm[0] + sm[1] + sm[2] + sm[3]) * scl;
}

__global__ void k_w1p(const float* __restrict__ w1, const float* __restrict__ b1,
                      const float* __restrict__ g2, const float* __restrict__ b2,
                      bf16* __restrict__ Wo, float* __restrict__ bo) {
    __shared__ float sm[4];
    int n = blockIdx.x, tid = threadIdx.x;
    float part = 0.f;
    for (int c = tid; c < CD; c += 128) {
        float wv = w1[(size_t)n * CD + c];
        part += wv * b2[c];
        Wo[(size_t)n * CD + c] = __float2bfloat16(wv * g2[c]);
    }
    #pragma unroll
    for (int o = 16; o > 0; o >>= 1) part += __shfl_down_sync(0xffffffffu, part, o);
    if ((tid & 31) == 0) sm[tid >> 5] = part;
    __syncthreads();
    if (tid == 0) bo[n] = b1[n] + sm[0] + sm[1] + sm[2] + sm[3];
}

__device__ __forceinline__ void reduce2_128(float& s0, float& s1, float* sm) {
    #pragma unroll
    for (int o = 16; o > 0; o >>= 1) {
        s0 += __shfl_down_sync(0xffffffffu, s0, o);
        s1 += __shfl_down_sync(0xffffffffu, s1, o);
    }
    int w = threadIdx.x >> 5;
    if ((threadIdx.x & 31) == 0) { sm[w] = s0; sm[4 + w] = s1; }
    __syncthreads();
    s0 = sm[0] + sm[1] + sm[2] + sm[3];
    s1 = sm[4] + sm[5] + sm[6] + sm[7];
    __syncthreads();
}

__device__ __forceinline__ int t_to_xrow(int t) {
    int w = t >> 6, l = t & 63;
    int b = w >> 6, wi = w & 63;
    int wy = wi >> 3, wx = wi & 7;
    int iy = l >> 3, ix = l & 7;
    return b * 4096 + (wy * 8 + iy) * 64 + wx * 8 + ix;
}

// ---------------- LN1 + window partition -> win(f32), u(bf16) --------------
__global__ void k_prep(const float* __restrict__ x,
                       const float* __restrict__ g1, const float* __restrict__ b1,
                       float* __restrict__ win, bf16* __restrict__ u) {
    __shared__ float sm[8];
    int t = blockIdx.x;
    size_t src = (size_t)t_to_xrow(t) * CD;
    int tid = threadIdx.x;

    float xv[3], s = 0.f, sq = 0.f;
    #pragma unroll
    for (int j = 0; j < 3; j++) {
        float v = x[src + tid + j * 128];
        xv[j] = v; s += v; sq += v * v;
    }
    reduce2_128(s, sq, sm);
    float m = s * (1.f / CD);
    float r = rsqrtf(sq * (1.f / CD) - m * m + 1e-5f);

    float wv[3]; s = 0.f; sq = 0.f;
    #pragma unroll
    for (int j = 0; j < 3; j++) {
        int c = tid + j * 128;
        float v = (xv[j] - m) * r * g1[c] + b1[c];
        wv[j] = v; s += v; sq += v * v;
    }
    reduce2_128(s, sq, sm);
    float m2 = s * (1.f / CD);
    float r2 = rsqrtf(sq * (1.f / CD) - m2 * m2 + 1e-5f);

    size_t dst = (size_t)t * CD;
    #pragma unroll
    for (int j = 0; j < 3; j++) {
        int c = tid + j * 128;
        win[dst + c] = wv[j];
        u[dst + c] = __float2bfloat16((wv[j] - m2) * r2);
    }
}

// ---------------- ldmatrix / mma wrappers ----------------
__device__ __forceinline__ void ldmx4(unsigned* r, const bf16* p) {
    unsigned a = (unsigned)__cvta_generic_to_shared(p);
    asm volatile("ldmatrix.sync.aligned.m8n8.x4.shared.b16 {%0,%1,%2,%3}, [%4];"
                 : "=r"(r[0]), "=r"(r[1]), "=r"(r[2]), "=r"(r[3]) : "r"(a));
}
__device__ __forceinline__ void mma16816(float* c, const unsigned* a, unsigned b0, unsigned b1) {
    asm volatile(
        "mma.sync.aligned.m16n8k16.row.col.f32.bf16.bf16.f32 "
        "{%0,%1,%2,%3}, {%4,%5,%6,%7}, {%8,%9}, {%0,%1,%2,%3};"
        : "+f"(c[0]), "+f"(c[1]), "+f"(c[2]), "+f"(c[3])
        : "r"(a[0]), "r"(a[1]), "r"(a[2]), "r"(a[3]), "r"(b0), "r"(b1));
}
__device__ __forceinline__ void cpa16(bf16* dst, const bf16* src) {
    unsigned d = (unsigned)__cvta_generic_to_shared(dst);
    asm volatile("cp.async.cg.shared.global [%0], [%1], 16;" :: "r"(d), "l"(src));
}

// ---------------- bf16 GEMM: 128x128x32, 3-stage cp.async, ldmatrix --------
// EPI: 0 = bias -> bf16, 1 = bias+GELU -> bf16, 2 = bias+res(f32) -> f32
#define SSTG 5120   // 128*40 elems per matrix per stage

template <int EPI>
__global__ void __launch_bounds__(256, 2)
k_mma2(const bf16* __restrict__ A, const bf16* __restrict__ Wt,
       const float* __restrict__ bias, const float* __restrict__ res,
       void* __restrict__ outv, int M, int N, int K) {
    extern __shared__ bf16 smem[];
    bf16* sA = smem;
    bf16* sB = smem + 3 * SSTG;

    int tid  = threadIdx.x;
    int lane = tid & 31, warp = tid >> 5;
    int wm = warp >> 2, wn = warp & 3;
    int gid = lane >> 2, tg = lane & 3;
    int t8 = lane >> 3, r8 = lane & 7;
    int bn = blockIdx.x, bm = blockIdx.y;

    const bf16* Ab = A  + (size_t)bm * 128 * K;
    const bf16* Bb = Wt + (size_t)bn * 128 * K;

    int lrow = tid >> 1;            // 0..127 (2 chunks per thread per matrix)
    int lc0 = (tid & 1) * 2;        // chunk pair: covers c in {lc0, lc0+1}

    float acc[4][4][4];
    #pragma unroll
    for (int i = 0; i < 4; i++)
        #pragma unroll
        for (int j = 0; j < 4; j++)
            #pragma unroll
            for (int r = 0; r < 4; r++) acc[i][j][r] = 0.f;

    int nst = K >> 5;
    // prologue: stages 0,1
    #pragma unroll
    for (int p = 0; p < 2; p++) {
        int k0 = p << 5;
        #pragma unroll
        for (int j = 0; j < 2; j++) {
            int c = lc0 + j;
            cpa16(sA + p * SSTG + lrow * 40 + c * 8, Ab + (size_t)lrow * K + k0 + c * 8);
            cpa16(sB + p * SSTG + lrow * 40 + c * 8, Bb + (size_t)lrow * K + k0 + c * 8);
        }
        asm volatile("cp.async.commit_group;");
    }

    for (int st = 0; st < nst; st++) {
        if (st + 1 < nst) asm volatile("cp.async.wait_group 1;");
        else              asm volatile("cp.async.wait_group 0;");
        __syncthreads();

        if (st + 2 < nst) {
            int k0 = (st + 2) << 5;
            int sp = (st + 2) % 3;
            #pragma unroll
            for (int j = 0; j < 2; j++) {
                int c = lc0 + j;
                cpa16(sA + sp * SSTG + lrow * 40 + c * 8, Ab + (size_t)lrow * K + k0 + c * 8);
                cpa16(sB + sp * SSTG + lrow * 40 + c * 8, Bb + (size_t)lrow * K + k0 + c * 8);
            }
            asm volatile("cp.async.commit_group;");
        } else {
            asm volatile("cp.async.commit_group;");
        }

        const bf16* As_ = sA + (st % 3) * SSTG;
        const bf16* Bs_ = sB + (st % 3) * SSTG;
        #pragma unroll
        for (int ks = 0; ks < 2; ks++) {
            int kk = ks * 16;
            unsigned af[4][4];
            #pragma unroll
            for (int mt = 0; mt < 4; mt++)
                ldmx4(af[mt], As_ + (wm * 64 + mt * 16 + (t8 & 1) * 8 + r8) * 40 + kk + (t8 >> 1) * 8);
            unsigned bfx[4][2];
            #pragma unroll
            for (int np = 0; np < 2; np++) {
                unsigned b4[4];
                ldmx4(b4, Bs_ + (wn * 32 + np * 16 + (t8 >> 1) * 8 + r8) * 40 + kk + (t8 & 1) * 8);
                bfx[np * 2][0] = b4[0]; bfx[np * 2][1] = b4[1];
                bfx[np * 2 + 1][0] = b4[2]; bfx[np * 2 + 1][1] = b4[3];
            }
            #pragma unroll
            for (int mt = 0; mt < 4; mt++)
                #pragma unroll
                for (int nt = 0; nt < 4; nt++)
                    mma16816(acc[mt][nt], af[mt], bfx[nt][0], bfx[nt][1]);
        }
    }

    float* outf = (float*)outv;
    bf16*  outb = (bf16*)outv;
    #pragma unroll
    for (int mt = 0; mt < 4; mt++) {
        int row0 = bm * 128 + wm * 64 + mt * 16 + gid;
        #pragma unroll
        for (int nt = 0; nt < 4; nt++) {
            int col = bn * 128 + wn * 32 + nt * 8 + tg * 2;
            float bi0 = bias[col], bi1 = bias[col + 1];
            #pragma unroll
            for (int h = 0; h < 2; h++) {
                int row = row0 + h * 8;
                size_t off = (size_t)row * N + col;
                float v0 = acc[mt][nt][h * 2 + 0] + bi0;
                float v1 = acc[mt][nt][h * 2 + 1] + bi1;
                if (EPI == 1) {
                    v0 = 0.5f * v0 * (1.f + erff(v0 * 0.70710678118654752f));
                    v1 = 0.5f * v1 * (1.f + erff(v1 * 0.70710678118654752f));
                }
                if (EPI == 2) {
                    float2 rr = *(const float2*)(res + off);
                    float2 ov; ov.x = v0 + rr.x; ov.y = v1 + rr.y;
                    *(float2*)(outf + off) = ov;
                } else {
                    __nv_bfloat162 ob;
                    ob.x = __float2bfloat16(v0); ob.y = __float2bfloat16(v1);
                    *(__nv_bfloat162*)(outb + off) = ob;
                }
            }
        }
    }
}

// ---------------- tensor-core attention: block = (window, head) ------------
__global__ void __launch_bounds__(128)
k_attn2(const bf16* __restrict__ qkv, bf16* __restrict__ o) {
    __shared__ bf16 Qs[64 * 40];
    __shared__ bf16 Ks[64 * 40];
    __shared__ bf16 Vt[32 * 72];
    int w = blockIdx.x, hd = blockIdx.y;
    int tid = threadIdx.x, lane = tid & 31, warp = tid >> 5;
    int gid = lane >> 2, tg = lane & 3;
    int t8 = lane >> 3, r8 = lane & 7;

    const bf16* base = qkv + (size_t)w * 64 * NQKV + hd * 32;
    for (int idx = tid; idx < 64 * 32; idx += 128) {
        int l = idx >> 5, d = idx & 31;
        const bf16* row = base + (size_t)l * NQKV;
        Qs[l * 40 + d] = row[d];
        Ks[l * 40 + d] = row[CD + d];
        Vt[d * 72 + l] = row[2 * CD + d];
    }
    __syncthreads();

    // S = Q @ K^T  (scale already folded into Q projection)
    unsigned aq[2][4];
    #pragma unroll
    for (int ks = 0; ks < 2; ks++)
        ldmx4(aq[ks], Qs + (warp * 16 + (t8 & 1) * 8 + r8) * 40 + ks * 16 + (t8 >> 1) * 8);

    float acc[8][4];
    #pragma unroll
    for (int i = 0; i < 8; i++)
        #pragma unroll
        for (int j = 0; j < 4; j++) acc[i][j] = 0.f;

    #pragma unroll
    for (int ks = 0; ks < 2; ks++) {
        #pragma unroll
        for (int np = 0; np < 4; np++) {
            unsigned b4[4];
            ldmx4(b4, Ks + (np * 16 + (t8 >> 1) * 8 + r8) * 40 + ks * 16 + (t8 & 1) * 8);
            mma16816(acc[np * 2],     aq[ks], b4[0], b4[1]);
            mma16816(acc[np * 2 + 1], aq[ks], b4[2], b4[3]);
        }
    }

    // softmax over 64 cols; rows gid (c0,c1) and gid+8 (c2,c3)
    float mx0 = -1e30f, mx1 = -1e30f;
    #pragma unroll
    for (int nt = 0; nt < 8; nt++) {
        mx0 = fmaxf(mx0, fmaxf(acc[nt][0], acc[nt][1]));
        mx1 = fmaxf(mx1, fmaxf(acc[nt][2], acc[nt][3]));
    }
    mx0 = fmaxf(mx0, __shfl_xor_sync(0xffffffffu, mx0, 1));
    mx0 = fmaxf(mx0, __shfl_xor_sync(0xffffffffu, mx0, 2));
    mx1 = fmaxf(mx1, __shfl_xor_sync(0xffffffffu, mx1, 1));
    mx1 = fmaxf(mx1, __shfl_xor_sync(0xffffffffu, mx1, 2));

    float s0 = 0.f, s1 = 0.f;
    #pragma unroll
    for (int nt = 0; nt < 8; nt++) {
        acc[nt][0] = __expf(acc[nt][0] - mx0); s0 += acc[nt][0];
        acc[nt][1] = __expf(acc[nt][1] - mx0); s0 += acc[nt][1];
        acc[nt][2] = __expf(acc[nt][2] - mx1); s1 += acc[nt][2];
        acc[nt][3] = __expf(acc[nt][3] - mx1); s1 += acc[nt][3];
    }
    s0 += __shfl_xor_sync(0xffffffffu, s0, 1);
    s0 += __shfl_xor_sync(0xffffffffu, s0, 2);
    s1 += __shfl_xor_sync(0xffffffffu, s1, 1);
    s1 += __shfl_xor_sync(0xffffffffu, s1, 2);
    float inv0 = 1.f / s0, inv1 = 1.f / s1;

    // P as A-fragments (C-layout == A-layout)
    unsigned pa[4][4];
    #pragma unroll
    for (int j = 0; j < 4; j++) {
        __nv_bfloat162 p0 = __floats2bfloat162_rn(acc[2*j][0]*inv0,   acc[2*j][1]*inv0);
        __nv_bfloat162 p1 = __floats2bfloat162_rn(acc[2*j][2]*inv1,   acc[2*j][3]*inv1);
        __nv_bfloat162 p2 = __floats2bfloat162_rn(acc[2*j+1][0]*inv0, acc[2*j+1][1]*inv0);
        __nv_bfloat162 p3 = __floats2bfloat162_rn(acc[2*j+1][2]*inv1, acc[2*j+1][3]*inv1);
        pa[j][0] = *(unsigned*)&p0; pa[j][1] = *(unsigned*)&p1;
        pa[j][2] = *(unsigned*)&p2; pa[j][3] = *(unsigned*)&p3;
    }

    float o4[4][4];
    #pragma unroll
    for (int i = 0; i < 4; i++)
        #pragma unroll
        for (int j = 0; j < 4; j++) o4[i][j] = 0.f;

    #pragma unroll
    for (int j = 0; j < 4; j++) {
        #pragma unroll
        for (int np = 0; np < 2; np++) {
            unsigned b4[4];
            ldmx4(b4, Vt + (np * 16 + (t8 >> 1) * 8 + r8) * 72 + j * 16 + (t8 & 1) * 8);
            mma16816(o4[np * 2],     pa[j], b4[0], b4[1]);
            mma16816(o4[np * 2 + 1], pa[j], b4[2], b4[3]);
        }
    }

    int r0 = w * 64 + warp * 16 + gid;
    #pragma unroll
    for (int nt = 0; nt < 4; nt++) {
        int col = hd * 32 + nt * 8 + tg * 2;
        __nv_bfloat162 ob;
        ob.x = __float2bfloat16(o4[nt][0]); ob.y = __float2bfloat16(o4[nt][1]);
        *(__nv_bfloat162*)(o + (size_t)r0 * CD + col) = ob;
        ob.x = __float2bfloat16(o4[nt][2]); ob.y = __float2bfloat16(o4[nt][3]);
        *(__nv_bfloat162*)(o + (size_t)(r0 + 8) * CD + col) = ob;
    }
}

// ---------------- nout-LN + reverse-window + residual + LN2(normalized) ----
__global__ void k_lnout_ln2(const float* __restrict__ ores, const float* __restrict__ x,
                            const float* __restrict__ gno, const float* __restrict__ bno,
                            float* __restrict__ x2, bf16* __restrict__ u2) {
    __shared__ float sm[8];
    int t = blockIdx.x;
    size_t src = (size_t)t * CD;
    size_t dst = (size_t)t_to_xrow(t) * CD;
    int tid = threadIdx.x;

    float ov[3], s = 0.f, sq = 0.f;
    #pragma unroll
    for (int j = 0; j < 3; j++) {
        float v = ores[src + tid + j * 128];
        ov[j] = v; s += v; sq += v * v;
    }
    reduce2_128(s, sq, sm);
    float m = s * (1.f / CD);
    float r = rsqrtf(sq * (1.f / CD) - m * m + 1e-5f);

    float xv2[3]; s = 0.f; sq = 0.f;
    #pragma unroll
    for (int j = 0; j < 3; j++) {
        int c = tid + j * 128;
        float a = (ov[j] - m) * r * gno[c] + bno[c];
        float xx = x[dst + c] + a;
        xv2[j] = xx; s += xx; sq += xx * xx;
    }
    reduce2_128(s, sq, sm);
    float m2 = s * (1.f / CD);
    float r2 = rsqrtf(sq * (1.f / CD) - m2 * m2 + 1e-5f);

    #pragma unroll
    for (int j = 0; j < 3; j++) {
        int c = tid + j * 128;
        x2[dst + c] = xv2[j];
        u2[dst + c] = __float2bfloat16((xv2[j] - m2) * r2);
    }
}

// ---------------- host launcher --------------------------------------------
extern "C" void kernel_launch(void* const* d_in, const int* in_sizes, int n_in,
                              void* d_out, int out_size) {
    const float* x   = (const float*)d_in[0];
    const float* g1  = (const float*)d_in[1];
    const float* b1  = (const float*)d_in[2];
    const float* gq  = (const float*)d_in[3];
    const float* bq  = (const float*)d_in[4];
    const float* gk  = (const float*)d_in[5];
    const float* bk  = (const float*)d_in[6];
    const float* gv  = (const float*)d_in[7];
    const float* bv  = (const float*)d_in[8];
    const float* gno = (const float*)d_in[9];
    const float* bno = (const float*)d_in[10];
    const float* ipw = (const float*)d_in[11];
    const float* ipb = (const float*)d_in[12];
    const float* opw = (const float*)d_in[13];
    const float* opb = (const float*)d_in[14];
    const float* g2n = (const float*)d_in[15];
    const float* b2n = (const float*)d_in[16];
    const float* w1  = (const float*)d_in[17];
    const float* b1f = (const float*)d_in[18];
    const float* w2  = (const float*)d_in[19];
    const float* b2f = (const float*)d_in[20];

    int B = in_sizes[0] / (64 * 64 * CD);
    int T = B * 64 * 64;
    int nW = B * 64;

    float *win, *ores, *x2, *bqkv, *b1p;
    bf16 *u, *qkv, *obf, *u2, *hbf, *wqkv, *opwb, *w1b, *w2b;
    cudaGetSymbolAddress((void**)&win,  g_win);
    cudaGetSymbolAddress((void**)&u,    g_u);
    cudaGetSymbolAddress((void**)&qkv,  g_qkv);
    cudaGetSymbolAddress((void**)&obf,  g_obf);
    cudaGetSymbolAddress((void**)&ores, g_ores);
    cudaGetSymbolAddress((void**)&x2,   g_x2);
    cudaGetSymbolAddress((void**)&u2,   g_u2);
    cudaGetSymbolAddress((void**)&hbf,  g_hbf);
    cudaGetSymbolAddress((void**)&wqkv, g_wqkv);
    cudaGetSymbolAddress((void**)&bqkv, g_bqkv);
    cudaGetSymbolAddress((void**)&opwb, g_opw);
    cudaGetSymbolAddress((void**)&w1b,  g_w1);
    cudaGetSymbolAddress((void**)&b1p,  g_b1p);
    cudaGetSymbolAddress((void**)&w2b,  g_w2);

    static int smem_set = 0;
    const int dynsmem = 3 * 2 * SSTG * (int)sizeof(bf16);   // 61440
    if (!smem_set) {
        cudaFuncSetAttribute(k_mma2<0>, cudaFuncAttributeMaxDynamicSharedMemorySize, dynsmem);
        cudaFuncSetAttribute(k_mma2<1>, cudaFuncAttributeMaxDynamicSharedMemorySize, dynsmem);
        cudaFuncSetAttribute(k_mma2<2>, cudaFuncAttributeMaxDynamicSharedMemorySize, dynsmem);
        smem_set = 1;
    }

    // 0) weight prep (affines + scale folded)
    k_wqkv<<<NQKV, 128>>>(ipw, ipb, gq, bq, gk, bk, gv, bv, wqkv, bqkv);
    k_w1p<<<FFD, 128>>>(w1, b1f, g2n, b2n, w1b, b1p);
    k_f2bf<<<(CD*CD  + 255) / 256, 256>>>(opw, opwb, CD*CD);
    k_f2bf<<<(CD*FFD + 255) / 256, 256>>>(w2,  w2b,  CD*FFD);

    // 1) LN1 + window partition
    k_prep<<<T, 128>>>(x, g1, b1, win, u);

    // 2) fused QKV projection (one GEMM, N=1152)
    dim3 thr(256);
    k_mma2<0><<<dim3(NQKV/128, T/128), thr, dynsmem>>>(u, wqkv, bqkv, nullptr, qkv, T, NQKV, CD);

    // 3) tensor-core windowed attention
    k_attn2<<<dim3(nW, NHEAD), 128>>>(qkv, obf);

    // 4) out_proj + residual(win)
    k_mma2<2><<<dim3(CD/128, T/128), thr, dynsmem>>>(obf, opwb, opb, win, ores, T, CD, CD);

    // 5) nout-LN + reverse window + residual + LN2
    k_lnout_ln2<<<T, 128>>>(ores, x, gno, bno, x2, u2);

    // 6) MLP
    k_mma2<1><<<dim3(FFD/128, T/128), thr, dynsmem>>>(u2, w1b, b1p, nullptr, hbf, T, FFD, CD);
    k_mma2<2><<<dim3(CD/128, T/128), thr, dynsmem>>>(hbf, w2b, b2f, x2, (float*)d_out, T, CD, FFD);
}